// round 1
// baseline (speedup 1.0000x reference)
#include <cuda_runtime.h>
#include <cstdint>

#define D 1024
#define WARPS_PER_BLOCK 8

typedef unsigned long long u64;

// ---------- packed f32x2 helpers (sm_103a) ----------
__device__ __forceinline__ u64 pack2(float a, float b) {
    u64 r; asm("mov.b64 %0, {%1, %2};" : "=l"(r) : "f"(a), "f"(b)); return r;
}
__device__ __forceinline__ void unpack2(u64 v, float& a, float& b) {
    asm("mov.b64 {%0, %1}, %2;" : "=f"(a), "=f"(b) : "l"(v));
}
__device__ __forceinline__ u64 add2(u64 a, u64 b) {
    u64 r; asm("add.rn.f32x2 %0, %1, %2;" : "=l"(r) : "l"(a), "l"(b)); return r;
}
__device__ __forceinline__ u64 mul2(u64 a, u64 b) {
    u64 r; asm("mul.rn.f32x2 %0, %1, %2;" : "=l"(r) : "l"(a), "l"(b)); return r;
}
// r = a*b + c
__device__ __forceinline__ u64 fma2(u64 a, u64 b, u64 c) {
    u64 r; asm("fma.rn.f32x2 %0, %1, %2, %3;" : "=l"(r) : "l"(a), "l"(b), "l"(c)); return r;
}

// In-register FWHT over the 32-element register axis.
// Pack k holds elements r=2k (lo), r=2k+1 (hi).
__device__ __forceinline__ void fwht32(u64 v[16]) {
    const u64 NEG1 = 0xBF800000BF800000ULL;  // (-1.f, -1.f)
    // stage stride 1: within-pack scalar butterflies
    #pragma unroll
    for (int k = 0; k < 16; k++) {
        float a, b; unpack2(v[k], a, b);
        v[k] = pack2(a + b, a - b);
    }
    // stages stride 2,4,8,16 -> pack stride 1,2,4,8 (packed f32x2)
    #pragma unroll
    for (int h = 1; h <= 8; h <<= 1) {
        #pragma unroll
        for (int k = 0; k < 16; k++) {
            if (!(k & h)) {
                u64 A = v[k], B = v[k + h];
                v[k]     = add2(A, B);
                v[k + h] = fma2(B, NEG1, A);  // A - B
            }
        }
    }
}

// swizzled element address: e = 32a + b -> 32a + (b ^ a)  (conflict-free transpose)
__device__ __forceinline__ int swz(int e) {
    return (e & ~31) | ((e & 31) ^ (e >> 5));
}

// Precomputed per-launch constants (allocation-free scratch)
__device__ int   g_Pphys[D];
__device__ float g_Sinv[D];

__global__ void fastfood_prep(const int* __restrict__ P, const float* __restrict__ S) {
    int i = blockIdx.x * blockDim.x + threadIdx.x;
    if (i < D) {
        g_Pphys[i] = swz(P[i]);
        g_Sinv[i]  = S[i] * 0.03125f;  // 1/sqrt(1024), SCALE=1
    }
}

__global__ __launch_bounds__(WARPS_PER_BLOCK * 32)
void fastfood_kernel(const float* __restrict__ x, const float* __restrict__ B,
                     const float* __restrict__ G, float* __restrict__ out, int nrows) {
    __shared__ float buf[WARPS_PER_BLOCK][D];
    const int warp = threadIdx.x >> 5;
    const int lane = threadIdx.x & 31;
    const int row  = blockIdx.x * WARPS_PER_BLOCK + warp;
    if (row >= nrows) return;
    float* sb = buf[warp];

    u64 v[16];

    // ---- load x*B, contiguous layout: lane owns elements [32*lane, 32*lane+32) ----
    const float4* x4 = reinterpret_cast<const float4*>(x) + (size_t)row * (D / 4) + lane * 8;
    const float4* B4 = reinterpret_cast<const float4*>(B) + lane * 8;
    #pragma unroll
    for (int i = 0; i < 8; i++) {
        float4 xa = __ldg(x4 + i);
        float4 ba = __ldg(B4 + i);
        v[2*i]   = mul2(pack2(xa.x, xa.y), pack2(ba.x, ba.y));
        v[2*i+1] = mul2(pack2(xa.z, xa.w), pack2(ba.z, ba.w));
    }

    // ---- WHT #1: low-bit axis in registers ----
    fwht32(v);

    // ---- transpose (contiguous e=32*lane+r  ->  strided e=32*r+lane), swizzled ----
    #pragma unroll
    for (int k = 0; k < 16; k++) {
        float a, b; unpack2(v[k], a, b);
        sb[32*lane + ((2*k)   ^ lane)] = a;
        sb[32*lane + ((2*k+1) ^ lane)] = b;
    }
    __syncwarp();
    #pragma unroll
    for (int k = 0; k < 16; k++) {
        float a = sb[32*(2*k)   + (lane ^ (2*k))];
        float b = sb[32*(2*k+1) + (lane ^ (2*k+1))];
        v[k] = pack2(a, b);
    }
    __syncwarp();

    // ---- WHT #1: high-bit axis in registers ----
    fwht32(v);

    // ---- scatter HBx to SMEM in (swizzled) element order for the permutation ----
    // pack k holds elements e = 32*(2k)+lane, 32*(2k+1)+lane
    #pragma unroll
    for (int k = 0; k < 16; k++) {
        float a, b; unpack2(v[k], a, b);
        sb[32*(2*k)   + (lane ^ (2*k))]   = a;
        sb[32*(2*k+1) + (lane ^ (2*k+1))] = b;
    }
    __syncwarp();

    // ---- gather with permutation (precomputed swizzled indices), multiply G ----
    const int4*   P4 = reinterpret_cast<const int4*>(g_Pphys) + lane * 8;
    const float4* G4 = reinterpret_cast<const float4*>(G) + lane * 8;
    #pragma unroll
    for (int i = 0; i < 8; i++) {
        int4   p = __ldg(P4 + i);
        float4 g = __ldg(G4 + i);
        float a0 = sb[p.x], a1 = sb[p.y], a2 = sb[p.z], a3 = sb[p.w];
        v[2*i]   = mul2(pack2(a0, a1), pack2(g.x, g.y));
        v[2*i+1] = mul2(pack2(a2, a3), pack2(g.z, g.w));
    }
    __syncwarp();

    // ---- WHT #2: low-bit axis ----
    fwht32(v);

    // ---- transpose again ----
    #pragma unroll
    for (int k = 0; k < 16; k++) {
        float a, b; unpack2(v[k], a, b);
        sb[32*lane + ((2*k)   ^ lane)] = a;
        sb[32*lane + ((2*k+1) ^ lane)] = b;
    }
    __syncwarp();
    #pragma unroll
    for (int k = 0; k < 16; k++) {
        float a = sb[32*(2*k)   + (lane ^ (2*k))];
        float b = sb[32*(2*k+1) + (lane ^ (2*k+1))];
        v[k] = pack2(a, b);
    }
    // no further smem use this row; no syncwarp needed

    // ---- WHT #2: high-bit axis ----
    fwht32(v);

    // ---- scale by S/32 and store (strided layout -> perfectly coalesced 128B stores) ----
    float* orow = out + (size_t)row * D;
    #pragma unroll
    for (int k = 0; k < 16; k++) {
        float s0 = __ldg(g_Sinv + 32*(2*k)   + lane);
        float s1 = __ldg(g_Sinv + 32*(2*k+1) + lane);
        u64 r = mul2(v[k], pack2(s0, s1));
        float a, b; unpack2(r, a, b);
        orow[32*(2*k)   + lane] = a;
        orow[32*(2*k+1) + lane] = b;
    }
}

extern "C" void kernel_launch(void* const* d_in, const int* in_sizes, int n_in,
                              void* d_out, int out_size) {
    const float* x = (const float*)d_in[0];
    const float* B = (const float*)d_in[1];
    const float* G = (const float*)d_in[2];
    const float* S = (const float*)d_in[3];
    const int*   P = (const int*)d_in[4];
    float* out = (float*)d_out;

    const int nrows = in_sizes[0] / D;

    fastfood_prep<<<(D + 255) / 256, 256>>>(P, S);

    const int blocks = (nrows + WARPS_PER_BLOCK - 1) / WARPS_PER_BLOCK;
    fastfood_kernel<<<blocks, WARPS_PER_BLOCK * 32>>>(x, B, G, out, nrows);
}

// round 2
// speedup vs baseline: 1.2525x; 1.2525x over previous
#include <cuda_runtime.h>
#include <cstdint>

#define D 1024
#define WARPS 4          // warps per block
#define RPW 2            // rows per warp

typedef unsigned long long u64;

// ---------- packed f32x2 helpers (sm_103a) ----------
__device__ __forceinline__ u64 pack2(float a, float b) {
    u64 r; asm("mov.b64 %0, {%1, %2};" : "=l"(r) : "f"(a), "f"(b)); return r;
}
__device__ __forceinline__ void unpack2(u64 v, float& a, float& b) {
    asm("mov.b64 {%0, %1}, %2;" : "=f"(a), "=f"(b) : "l"(v));
}
__device__ __forceinline__ u64 add2(u64 a, u64 b) {
    u64 r; asm("add.rn.f32x2 %0, %1, %2;" : "=l"(r) : "l"(a), "l"(b)); return r;
}
__device__ __forceinline__ u64 mul2(u64 a, u64 b) {
    u64 r; asm("mul.rn.f32x2 %0, %1, %2;" : "=l"(r) : "l"(a), "l"(b)); return r;
}
__device__ __forceinline__ u64 fma2(u64 a, u64 b, u64 c) {
    u64 r; asm("fma.rn.f32x2 %0, %1, %2, %3;" : "=l"(r) : "l"(a), "l"(b), "l"(c)); return r;
}

// In-register FWHT over the 32-element register axis (pack k = elems 2k,2k+1)
__device__ __forceinline__ void fwht32(u64 v[16]) {
    const u64 NEG1 = 0xBF800000BF800000ULL;  // (-1.f, -1.f)
    #pragma unroll
    for (int k = 0; k < 16; k++) {
        float a, b; unpack2(v[k], a, b);
        v[k] = pack2(a + b, a - b);
    }
    #pragma unroll
    for (int h = 1; h <= 8; h <<= 1) {
        #pragma unroll
        for (int k = 0; k < 16; k++) {
            if (!(k & h)) {
                u64 A = v[k], B = v[k + h];
                v[k]     = add2(A, B);
                v[k + h] = fma2(B, NEG1, A);
            }
        }
    }
}

// Exchange layout: logical element i (10 bits) lives at physical float index
//   phys(i) = (i>>5)*32 + ((((i&31)>>2) + (i>>5)) & 7)*4 + (i&3)
// -> row = i>>5, float4-column rotated by row. Properties:
//    * reader lane reads its 32 elements {i = lane*32 + 0..31} as 8 conflict-free LDS.128
//    * a scalar write instruction that writes one full row hits all 32 banks

// Precomputed tables (allocation-free scratch)
__device__ int   g_Qt[D];   // Qt[(e&31)*32 + (e>>5)] = phys(Pinv[e])
__device__ float g_St[D];   // St[(t&31)*32 + (t>>5)] = S[t]/32

__global__ void fastfood_prep(const int* __restrict__ P, const float* __restrict__ S) {
    int i = blockIdx.x * blockDim.x + threadIdx.x;
    if (i < D) {
        int e = P[i];
        int phys = (i >> 5) * 32 + (((((i & 31) >> 2) + (i >> 5)) & 7) << 2) + (i & 3);
        g_Qt[(e & 31) * 32 + (e >> 5)] = phys;
        g_St[(i & 31) * 32 + (i >> 5)] = S[i] * 0.03125f;  // 1/sqrt(1024), SCALE=1
    }
}

__global__ __launch_bounds__(WARPS * 32, 4)
void fastfood_kernel(const float* __restrict__ x, const float* __restrict__ B,
                     const float* __restrict__ G, float* __restrict__ out, int nrows) {
    __shared__ float buf[WARPS][RPW][D];
    const int warp = threadIdx.x >> 5;
    const int lane = threadIdx.x & 31;
    const int pair = blockIdx.x * WARPS + warp;
    if (pair * RPW >= nrows) return;

    float* sa = buf[warp][0];
    float* sb = buf[warp][1];
    const float4* sa4 = reinterpret_cast<const float4*>(sa);
    const float4* sb4 = reinterpret_cast<const float4*>(sb);

    u64 va[16], vb[16];

    // ---- load x*B (contiguous ownership e = lane*32 + k), all float4 ----
    const float4* Bv = reinterpret_cast<const float4*>(B) + lane * 8;
    const float4* xa = reinterpret_cast<const float4*>(x) + (size_t)(pair * RPW) * (D / 4) + lane * 8;
    const float4* xb = xa + (D / 4);
    #pragma unroll
    for (int c4 = 0; c4 < 8; c4++) {
        float4 bb = Bv[c4];
        float4 fa = xa[c4];
        float4 fb = xb[c4];
        u64 b01 = pack2(bb.x, bb.y), b23 = pack2(bb.z, bb.w);
        va[2*c4]   = mul2(pack2(fa.x, fa.y), b01);
        va[2*c4+1] = mul2(pack2(fa.z, fa.w), b23);
        vb[2*c4]   = mul2(pack2(fb.x, fb.y), b01);
        vb[2*c4+1] = mul2(pack2(fb.z, fb.w), b23);
    }

    // ---- WHT #1 low 5 bits (register axis) ----
    fwht32(va); fwht32(vb);

    // ---- exchange 1 (transpose): scalar row-writes (conflict-free), float4 reads ----
    #pragma unroll
    for (int kk = 0; kk < 16; kk++) {
        float a0, a1, b0, b1;
        unpack2(va[kk], a0, a1);
        unpack2(vb[kk], b0, b1);
        const int r0 = 2*kk, r1 = 2*kk + 1;
        const int ad0 = r0*32 + ((((lane >> 2) + r0) & 7) << 2) + (lane & 3);
        const int ad1 = r1*32 + ((((lane >> 2) + r1) & 7) << 2) + (lane & 3);
        sa[ad0] = a0; sa[ad1] = a1;
        sb[ad0] = b0; sb[ad1] = b1;
    }
    __syncwarp();
    #pragma unroll
    for (int c4 = 0; c4 < 8; c4++) {
        const int idx = lane * 8 + ((c4 + lane) & 7);
        float4 fa = sa4[idx];
        float4 fb = sb4[idx];
        va[2*c4]   = pack2(fa.x, fa.y);
        va[2*c4+1] = pack2(fa.z, fa.w);
        vb[2*c4]   = pack2(fb.x, fb.y);
        vb[2*c4+1] = pack2(fb.z, fb.w);
    }

    // ---- WHT #1 high 5 bits (thread now owns e = m*32 + lane) ----
    fwht32(va); fwht32(vb);
    __syncwarp();  // all reads of exchange-1 data done before scatter overwrites

    // ---- exchange 2 (permutation): scatter to precomputed phys targets ----
    const int4* Q4 = reinterpret_cast<const int4*>(g_Qt) + lane * 8;
    #pragma unroll
    for (int c4 = 0; c4 < 8; c4++) {
        int4 q = Q4[c4];
        float a0, a1, a2, a3, b0, b1, b2, b3;
        unpack2(va[2*c4],   a0, a1);
        unpack2(va[2*c4+1], a2, a3);
        unpack2(vb[2*c4],   b0, b1);
        unpack2(vb[2*c4+1], b2, b3);
        sa[q.x] = a0; sa[q.y] = a1; sa[q.z] = a2; sa[q.w] = a3;
        sb[q.x] = b0; sb[q.y] = b1; sb[q.z] = b2; sb[q.w] = b3;
    }
    __syncwarp();

    // ---- gather back contiguous (float4) and multiply G ----
    const float4* Gv = reinterpret_cast<const float4*>(G) + lane * 8;
    #pragma unroll
    for (int c4 = 0; c4 < 8; c4++) {
        const int idx = lane * 8 + ((c4 + lane) & 7);
        float4 fa = sa4[idx];
        float4 fb = sb4[idx];
        float4 g  = Gv[c4];
        u64 g01 = pack2(g.x, g.y), g23 = pack2(g.z, g.w);
        va[2*c4]   = mul2(pack2(fa.x, fa.y), g01);
        va[2*c4+1] = mul2(pack2(fa.z, fa.w), g23);
        vb[2*c4]   = mul2(pack2(fb.x, fb.y), g01);
        vb[2*c4+1] = mul2(pack2(fb.z, fb.w), g23);
    }

    // ---- WHT #2 low 5 bits ----
    fwht32(va); fwht32(vb);
    __syncwarp();

    // ---- exchange 3 (transpose) ----
    #pragma unroll
    for (int kk = 0; kk < 16; kk++) {
        float a0, a1, b0, b1;
        unpack2(va[kk], a0, a1);
        unpack2(vb[kk], b0, b1);
        const int r0 = 2*kk, r1 = 2*kk + 1;
        const int ad0 = r0*32 + ((((lane >> 2) + r0) & 7) << 2) + (lane & 3);
        const int ad1 = r1*32 + ((((lane >> 2) + r1) & 7) << 2) + (lane & 3);
        sa[ad0] = a0; sa[ad1] = a1;
        sb[ad0] = b0; sb[ad1] = b1;
    }
    __syncwarp();
    #pragma unroll
    for (int c4 = 0; c4 < 8; c4++) {
        const int idx = lane * 8 + ((c4 + lane) & 7);
        float4 fa = sa4[idx];
        float4 fb = sb4[idx];
        va[2*c4]   = pack2(fa.x, fa.y);
        va[2*c4+1] = pack2(fa.z, fa.w);
        vb[2*c4]   = pack2(fb.x, fb.y);
        vb[2*c4+1] = pack2(fb.z, fb.w);
    }

    // ---- WHT #2 high 5 bits ----
    fwht32(va); fwht32(vb);

    // ---- scale by S/32 (pre-transposed table, float4) and store ----
    const float4* Sv = reinterpret_cast<const float4*>(g_St) + lane * 8;
    float* oa = out + (size_t)(pair * RPW) * D;
    float* ob = oa + D;
    #pragma unroll
    for (int c4 = 0; c4 < 8; c4++) {
        float4 s = Sv[c4];
        u64 s01 = pack2(s.x, s.y), s23 = pack2(s.z, s.w);
        u64 ra0 = mul2(va[2*c4],   s01);
        u64 ra1 = mul2(va[2*c4+1], s23);
        u64 rb0 = mul2(vb[2*c4],   s01);
        u64 rb1 = mul2(vb[2*c4+1], s23);
        float p0, p1, p2, p3;
        unpack2(ra0, p0, p1); unpack2(ra1, p2, p3);
        oa[(4*c4+0)*32 + lane] = p0;
        oa[(4*c4+1)*32 + lane] = p1;
        oa[(4*c4+2)*32 + lane] = p2;
        oa[(4*c4+3)*32 + lane] = p3;
        unpack2(rb0, p0, p1); unpack2(rb1, p2, p3);
        ob[(4*c4+0)*32 + lane] = p0;
        ob[(4*c4+1)*32 + lane] = p1;
        ob[(4*c4+2)*32 + lane] = p2;
        ob[(4*c4+3)*32 + lane] = p3;
    }
}

extern "C" void kernel_launch(void* const* d_in, const int* in_sizes, int n_in,
                              void* d_out, int out_size) {
    const float* x = (const float*)d_in[0];
    const float* B = (const float*)d_in[1];
    const float* G = (const float*)d_in[2];
    const float* S = (const float*)d_in[3];
    const int*   P = (const int*)d_in[4];
    float* out = (float*)d_out;

    const int nrows = in_sizes[0] / D;

    fastfood_prep<<<(D + 255) / 256, 256>>>(P, S);

    const int rows_per_block = WARPS * RPW;
    const int blocks = (nrows + rows_per_block - 1) / rows_per_block;
    fastfood_kernel<<<blocks, WARPS * 32>>>(x, B, G, out, nrows);
}